// round 1
// baseline (speedup 1.0000x reference)
#include <cuda_runtime.h>

#define BB 128
#define TT 152
#define II 75
#define HH 256
#define LL 16
#define CC 625
#define G4 1024
#define EPSV 1e-5f

// ---------------- device scratch (no allocation allowed) ----------------
__device__ float d_wi[(size_t)TT * G4 * BB];   // [t][gate_col][b]  (~76 MB)
__device__ float d_x0[(size_t)TT * BB * HH];   // ping
__device__ float d_x1[(size_t)TT * BB * HH];   // pong
__device__ unsigned int d_bar;

__global__ void reset_bar_kernel() { d_bar = 0u; }

__device__ __forceinline__ float sigm(float x) { return 1.f / (1.f + __expf(-x)); }

// =====================================================================
// Projection + BatchNorm kernel:
//   wi = x[t] @ Wi  (B x K @ K x 1024), BN over batch per (t,col),
//   out = bn(wi)*g_ih + b_ih + bias, stored as d_wi[t][col][b].
// grid: (T, 16 col-blocks of 64), block 256.
// =====================================================================
__launch_bounds__(256) __global__ void projbn_kernel(
    const float* __restrict__ seq, const float* __restrict__ Wi,
    const float* __restrict__ gih, const float* __restrict__ bih,
    const float* __restrict__ bias, int K, int in_sel)
{
    extern __shared__ float sm[];
    float* xs    = sm;               // [64][129] transposed x chunk
    float* ws    = sm + 8256;        // [64][65]  W chunk
    float* red_s = ws + 4160;        // [16][64]
    float* red_q = red_s + 1024;     // [16][64]
    float* alpha = red_q + 1024;     // [64]
    float* beta  = alpha + 64;       // [64]
    float* st    = xs;               // alias (reused after GEMM): [64][129]

    const int tid = threadIdx.x;
    const int cg = tid & 15;          // col group (4 cols)
    const int bg = tid >> 4;          // batch group (8 rows)
    const int t = blockIdx.x;
    const int col0 = blockIdx.y * 64;

    float acc[8][4];
#pragma unroll
    for (int i = 0; i < 8; i++)
#pragma unroll
        for (int j = 0; j < 4; j++) acc[i][j] = 0.f;

    for (int k0 = 0; k0 < K; k0 += 64) {
        int kc = K - k0; if (kc > 64) kc = 64;
        // load x chunk (zero-padded), transposed: xs[kk][b]
        for (int idx = tid; idx < 64 * 128; idx += 256) {
            int kk = idx & 63, b = idx >> 6;
            float v = 0.f;
            if (kk < kc) {
                int k = k0 + kk;
                if (in_sel < 0)      v = seq[(b * TT + t) * II + k];
                else if (in_sel==0)  v = d_x0[((size_t)t * BB + b) * HH + k];
                else                 v = d_x1[((size_t)t * BB + b) * HH + k];
            }
            xs[kk * 129 + b] = v;
        }
        // load W chunk: ws[kk][c]
        for (int idx = tid; idx < 64 * 64; idx += 256) {
            int c = idx & 63, kk = idx >> 6;
            ws[kk * 65 + c] = (kk < kc) ? Wi[(k0 + kk) * G4 + col0 + c] : 0.f;
        }
        __syncthreads();
#pragma unroll 4
        for (int kk = 0; kk < 64; kk++) {
            float w0 = ws[kk * 65 + cg * 4 + 0];
            float w1 = ws[kk * 65 + cg * 4 + 1];
            float w2 = ws[kk * 65 + cg * 4 + 2];
            float w3 = ws[kk * 65 + cg * 4 + 3];
#pragma unroll
            for (int i = 0; i < 8; i++) {
                float xv = xs[kk * 129 + bg * 8 + i];
                acc[i][0] += xv * w0;
                acc[i][1] += xv * w1;
                acc[i][2] += xv * w2;
                acc[i][3] += xv * w3;
            }
        }
        __syncthreads();
    }

    // partial batch sums per column
#pragma unroll
    for (int j = 0; j < 4; j++) {
        float ls = 0.f, lq = 0.f;
#pragma unroll
        for (int i = 0; i < 8; i++) { ls += acc[i][j]; lq += acc[i][j] * acc[i][j]; }
        red_s[bg * 64 + cg * 4 + j] = ls;
        red_q[bg * 64 + cg * 4 + j] = lq;
    }
    __syncthreads();
    if (tid < 64) {
        float s = 0.f, q = 0.f;
        for (int g = 0; g < 16; g++) { s += red_s[g * 64 + tid]; q += red_q[g * 64 + tid]; }
        float mean = s * (1.f / 128.f);
        float var  = q * (1.f / 128.f) - mean * mean;
        float rs = rsqrtf(var + EPSV);
        int col = col0 + tid;
        float a = gih[col] * rs;
        alpha[tid] = a;
        beta[tid] = bih[col] + bias[col] - mean * a;
    }
    __syncthreads();
    // stage acc into smem (aliasing xs) for coalesced output
#pragma unroll
    for (int j = 0; j < 4; j++)
#pragma unroll
        for (int i = 0; i < 8; i++)
            st[(cg * 4 + j) * 129 + (bg * 8 + i)] = acc[i][j];
    __syncthreads();
    for (int idx = tid; idx < 64 * 128; idx += 256) {
        int b = idx & 127, c = idx >> 7;
        d_wi[((size_t)t * G4 + col0 + c) * BB + b] = st[c * 129 + b] * alpha[c] + beta[c];
    }
}

// =====================================================================
// Persistent recurrence kernel: one launch per layer, all T steps.
// grid 128 CTAs (<= SM count, 1 CTA/SM via smem), block 256.
// CTA owns 2 h-columns (8 gate columns) for the full batch.
// One global spin-barrier per timestep.
// =====================================================================
__launch_bounds__(256, 1) __global__ void recur_kernel(
    const float* __restrict__ Whh_l,
    const float* __restrict__ ghh_l, const float* __restrict__ bhh_l,
    const float* __restrict__ gc_l,  const float* __restrict__ bc_l,
    int out_sel)
{
    extern __shared__ float sm[];
    float* hsm = sm;                 // [256][129]  h(t-1), k-major
    float* wsm = sm + 256 * 129;     // [256][8]    Whh slice
    float* red = wsm + 2048;         // phase1: 64, phase2: 16

    float* hsbuf = out_sel ? d_x1 : d_x0;

    const int tid = threadIdx.x;
    const int hcl = tid >> 7;                // 0/1
    const int b   = tid & 127;
    const int warp = tid >> 5, lane = tid & 31;
    const int hcol = blockIdx.x * 2 + hcl;

    // Whh slice into smem: wsm[k*8 + q], q = hcl*4 + gate
    for (int idx = tid; idx < 256 * 8; idx += 256) {
        int k = idx >> 3, q = idx & 7;
        int hc = blockIdx.x * 2 + (q >> 2);
        int j = q & 3;
        wsm[idx] = Whh_l[k * G4 + j * HH + hc];
    }

    float ghh[4], bhh[4];
#pragma unroll
    for (int j = 0; j < 4; j++) {
        ghh[j] = ghh_l[j * HH + hcol];
        bhh[j] = bhh_l[j * HH + hcol];
    }
    const float gcv = gc_l[hcol], bcv = bc_l[hcol];
    float c = 0.f;

    __syncthreads();

    const float4* w4 = (const float4*)wsm;
    volatile unsigned int* vb = &d_bar;

    for (int t = 0; t < TT; t++) {
        // prefetch this step's bn_wi (coalesced: b contiguous)
        float wiv[4];
#pragma unroll
        for (int j = 0; j < 4; j++)
            wiv[j] = d_wi[((size_t)t * G4 + j * HH + hcol) * BB + b];

        float acc[4] = {0.f, 0.f, 0.f, 0.f};
        if (t > 0) {
            const float4* hp4 = (const float4*)(hsbuf + (size_t)(t - 1) * BB * HH);
            for (int idx = tid; idx < 8192; idx += 256) {
                float4 v = hp4[idx];
                int bb = idx >> 6;
                int k = (idx & 63) * 4;
                hsm[(k + 0) * 129 + bb] = v.x;
                hsm[(k + 1) * 129 + bb] = v.y;
                hsm[(k + 2) * 129 + bb] = v.z;
                hsm[(k + 3) * 129 + bb] = v.w;
            }
            __syncthreads();
#pragma unroll 8
            for (int k = 0; k < 256; k++) {
                float hv = hsm[k * 129 + b];
                float4 w = w4[k * 2 + hcl];
                acc[0] += hv * w.x;
                acc[1] += hv * w.y;
                acc[2] += hv * w.z;
                acc[3] += hv * w.w;
            }
        }

        // ---- BN over batch per gate column (group = 4 warps sharing hcl) ----
        float s[4], q[4];
#pragma unroll
        for (int j = 0; j < 4; j++) { s[j] = acc[j]; q[j] = acc[j] * acc[j]; }
#pragma unroll
        for (int o = 16; o; o >>= 1)
#pragma unroll
            for (int j = 0; j < 4; j++) {
                s[j] += __shfl_xor_sync(0xffffffffu, s[j], o);
                q[j] += __shfl_xor_sync(0xffffffffu, q[j], o);
            }
        if (lane == 0)
#pragma unroll
            for (int j = 0; j < 4; j++) {
                red[warp * 8 + j] = s[j];
                red[warp * 8 + 4 + j] = q[j];
            }
        __syncthreads();
        float sg[4];
        {
            float S[4] = {0,0,0,0}, Q[4] = {0,0,0,0};
            int w0 = hcl * 4;
#pragma unroll
            for (int w = 0; w < 4; w++)
#pragma unroll
                for (int j = 0; j < 4; j++) {
                    S[j] += red[(w0 + w) * 8 + j];
                    Q[j] += red[(w0 + w) * 8 + 4 + j];
                }
#pragma unroll
            for (int j = 0; j < 4; j++) {
                float mean = S[j] * (1.f / 128.f);
                float var = Q[j] * (1.f / 128.f) - mean * mean;
                float rs = rsqrtf(var + EPSV);
                sg[j] = (acc[j] - mean) * rs * ghh[j] + bhh[j] + wiv[j];
            }
        }
        // gate order: f, i, o, g
        float fg = sigm(sg[0]);
        float ig = sigm(sg[1]);
        float og = sigm(sg[2]);
        float gg = tanhf(sg[3]);
        c = fg * c + ig * gg;

        // ---- BN(c) over batch per h column ----
        float cs = c, cq = c * c;
#pragma unroll
        for (int o = 16; o; o >>= 1) {
            cs += __shfl_xor_sync(0xffffffffu, cs, o);
            cq += __shfl_xor_sync(0xffffffffu, cq, o);
        }
        if (lane == 0) { red[64 + warp * 2] = cs; red[64 + warp * 2 + 1] = cq; }
        __syncthreads();
        float Sc = 0.f, Qc = 0.f;
        {
            int w0 = hcl * 4;
#pragma unroll
            for (int w = 0; w < 4; w++) { Sc += red[64 + (w0 + w) * 2]; Qc += red[64 + (w0 + w) * 2 + 1]; }
        }
        float mc = Sc * (1.f / 128.f);
        float vc = Qc * (1.f / 128.f) - mc * mc;
        float cn = (c - mc) * rsqrtf(vc + EPSV) * gcv + bcv;
        float h = og * tanhf(cn);

        hsbuf[(size_t)t * BB * HH + b * HH + hcol] = h;

        if (t < TT - 1) {
            __threadfence();
            __syncthreads();
            if (tid == 0) {
                atomicAdd(&d_bar, 1u);
                unsigned int target = gridDim.x * (unsigned)(t + 1);
                while (*vb < target) { }
                __threadfence();
            }
            __syncthreads();
        }
    }
}

// =====================================================================
// Final: out = softmax(h_last @ W_lin + b_lin). grid 128 (batch), block 256.
// =====================================================================
__launch_bounds__(256) __global__ void final_kernel(
    int xsel, const float* __restrict__ Wlin, const float* __restrict__ blin,
    float* __restrict__ out)
{
    __shared__ float xr[256];
    __shared__ float lg[CC];
    __shared__ float rbuf[8];
    const float* hs = (xsel ? d_x1 : d_x0);
    const float* xlast = hs + (size_t)(TT - 1) * BB * HH + blockIdx.x * HH;
    int tid = threadIdx.x, warp = tid >> 5, lane = tid & 31;

    xr[tid] = xlast[tid];
    __syncthreads();

    float lmax = -1e30f;
    for (int cidx = tid; cidx < CC; cidx += 256) {
        float a = blin[cidx];
#pragma unroll 4
        for (int k = 0; k < 256; k++) a += xr[k] * Wlin[k * CC + cidx];
        lg[cidx] = a;
        lmax = fmaxf(lmax, a);
    }
#pragma unroll
    for (int o = 16; o; o >>= 1) lmax = fmaxf(lmax, __shfl_xor_sync(0xffffffffu, lmax, o));
    if (lane == 0) rbuf[warp] = lmax;
    __syncthreads();
    float M = rbuf[0];
#pragma unroll
    for (int w = 1; w < 8; w++) M = fmaxf(M, rbuf[w]);
    __syncthreads();

    float lsum = 0.f;
    for (int cidx = tid; cidx < CC; cidx += 256) {
        float e = __expf(lg[cidx] - M);
        lg[cidx] = e;
        lsum += e;
    }
#pragma unroll
    for (int o = 16; o; o >>= 1) lsum += __shfl_xor_sync(0xffffffffu, lsum, o);
    if (lane == 0) rbuf[warp] = lsum;
    __syncthreads();
    float S = 0.f;
#pragma unroll
    for (int w = 0; w < 8; w++) S += rbuf[w];
    float inv = 1.f / S;
    for (int cidx = tid; cidx < CC; cidx += 256)
        out[blockIdx.x * CC + cidx] = lg[cidx] * inv;
}

// =====================================================================
extern "C" void kernel_launch(void* const* d_in, const int* in_sizes, int n_in,
                              void* d_out, int out_size)
{
    const float* seq  = (const float*)d_in[0];
    const float* Wih0 = (const float*)d_in[1];
    const float* Wih  = (const float*)d_in[2];
    const float* Whh  = (const float*)d_in[3];
    const float* bias = (const float*)d_in[4];
    const float* gih  = (const float*)d_in[5];
    const float* bih  = (const float*)d_in[6];
    const float* ghh  = (const float*)d_in[7];
    const float* bhh  = (const float*)d_in[8];
    const float* gc   = (const float*)d_in[9];
    const float* bc   = (const float*)d_in[10];
    const float* Wlin = (const float*)d_in[11];
    const float* blin = (const float*)d_in[12];
    float* out = (float*)d_out;

    const int PROJ_SMEM  = (8256 + 4160 + 1024 + 1024 + 64 + 64) * 4;   // 58368 B
    const int RECUR_SMEM = (256 * 129 + 2048 + 96) * 4;                 // 140672 B

    cudaFuncSetAttribute((const void*)projbn_kernel,
                         cudaFuncAttributeMaxDynamicSharedMemorySize, PROJ_SMEM);
    cudaFuncSetAttribute((const void*)recur_kernel,
                         cudaFuncAttributeMaxDynamicSharedMemorySize, RECUR_SMEM);

    for (int l = 0; l < LL; l++) {
        const float* Wi = (l == 0) ? Wih0 : (Wih + (size_t)(l - 1) * HH * G4);
        int K = (l == 0) ? II : HH;
        int in_sel = (l == 0) ? -1 : ((l - 1) & 1);
        projbn_kernel<<<dim3(TT, 16), 256, PROJ_SMEM>>>(
            seq, Wi, gih + l * G4, bih + l * G4, bias + l * G4, K, in_sel);
        reset_bar_kernel<<<1, 1>>>();
        recur_kernel<<<128, 256, RECUR_SMEM>>>(
            Whh + (size_t)l * HH * G4,
            ghh + l * G4, bhh + l * G4, gc + l * HH, bc + l * HH, l & 1);
    }
    final_kernel<<<128, 256>>>((LL - 1) & 1, Wlin, blin, out);
}

// round 2
// speedup vs baseline: 1.2664x; 1.2664x over previous
#include <cuda_runtime.h>

#define BB 128
#define TT 152
#define II 75
#define HH 256
#define LL 16
#define CC 625
#define G4 1024
#define EPSV 1e-5f

// ---------------- device scratch (no allocation allowed) ----------------
__device__ float d_wi[(size_t)TT * G4 * BB];   // [t][gate_col][b]
__device__ float d_x0[(size_t)TT * HH * BB];   // k-major: [t][k][b]  (ping)
__device__ float d_x1[(size_t)TT * HH * BB];   // k-major: [t][k][b]  (pong)
__device__ unsigned int d_bar;

__global__ void reset_bar_kernel() { d_bar = 0u; }

__device__ __forceinline__ float sigm(float x) { return 1.f / (1.f + __expf(-x)); }

// =====================================================================
// Projection + BatchNorm kernel (unchanged GEMM core — already at FFMA peak):
//   wi = x[t] @ Wi  (B x K @ K x 1024), BN over batch per (t,col),
//   out = bn(wi)*g_ih + b_ih + bias, stored as d_wi[t][col][b].
// grid: (T, 16 col-blocks of 64), block 256.
// x source for l>0 is now k-major [t][k][b] -> fill mapping swapped.
// =====================================================================
__launch_bounds__(256) __global__ void projbn_kernel(
    const float* __restrict__ seq, const float* __restrict__ Wi,
    const float* __restrict__ gih, const float* __restrict__ bih,
    const float* __restrict__ bias, int K, int in_sel)
{
    extern __shared__ float sm[];
    float* xs    = sm;               // [64][129] x chunk, [kk][b]
    float* ws    = sm + 8256;        // [64][65]  W chunk
    float* red_s = ws + 4160;        // [16][64]
    float* red_q = red_s + 1024;     // [16][64]
    float* alpha = red_q + 1024;     // [64]
    float* beta  = alpha + 64;       // [64]
    float* st    = xs;               // alias (reused after GEMM): [64][129]

    const int tid = threadIdx.x;
    const int cg = tid & 15;          // col group (4 cols)
    const int bg = tid >> 4;          // batch group (8 rows)
    const int t = blockIdx.x;
    const int col0 = blockIdx.y * 64;

    float acc[8][4];
#pragma unroll
    for (int i = 0; i < 8; i++)
#pragma unroll
        for (int j = 0; j < 4; j++) acc[i][j] = 0.f;

    for (int k0 = 0; k0 < K; k0 += 64) {
        int kc = K - k0; if (kc > 64) kc = 64;
        // load x chunk (zero-padded): xs[kk][b]
        if (in_sel < 0) {
            // seq: [b][t][k] -> kk-fast mapping is coalesced in k
            for (int idx = tid; idx < 64 * 128; idx += 256) {
                int kk = idx & 63, b = idx >> 6;
                float v = 0.f;
                if (kk < kc) v = seq[(b * TT + t) * II + (k0 + kk)];
                xs[kk * 129 + b] = v;
            }
        } else {
            // h: k-major [t][k][b] -> b-fast mapping is coalesced in b
            const float* src = in_sel ? d_x1 : d_x0;
            for (int idx = tid; idx < 64 * 128; idx += 256) {
                int b = idx & 127, kk = idx >> 7;
                float v = 0.f;
                if (kk < kc) v = src[((size_t)t * HH + (k0 + kk)) * BB + b];
                xs[kk * 129 + b] = v;
            }
        }
        // load W chunk: ws[kk][c]
        for (int idx = tid; idx < 64 * 64; idx += 256) {
            int c = idx & 63, kk = idx >> 6;
            ws[kk * 65 + c] = (kk < kc) ? Wi[(k0 + kk) * G4 + col0 + c] : 0.f;
        }
        __syncthreads();
#pragma unroll 4
        for (int kk = 0; kk < 64; kk++) {
            float w0 = ws[kk * 65 + cg * 4 + 0];
            float w1 = ws[kk * 65 + cg * 4 + 1];
            float w2 = ws[kk * 65 + cg * 4 + 2];
            float w3 = ws[kk * 65 + cg * 4 + 3];
#pragma unroll
            for (int i = 0; i < 8; i++) {
                float xv = xs[kk * 129 + bg * 8 + i];
                acc[i][0] += xv * w0;
                acc[i][1] += xv * w1;
                acc[i][2] += xv * w2;
                acc[i][3] += xv * w3;
            }
        }
        __syncthreads();
    }

    // partial batch sums per column
#pragma unroll
    for (int j = 0; j < 4; j++) {
        float ls = 0.f, lq = 0.f;
#pragma unroll
        for (int i = 0; i < 8; i++) { ls += acc[i][j]; lq += acc[i][j] * acc[i][j]; }
        red_s[bg * 64 + cg * 4 + j] = ls;
        red_q[bg * 64 + cg * 4 + j] = lq;
    }
    __syncthreads();
    if (tid < 64) {
        float s = 0.f, q = 0.f;
        for (int g = 0; g < 16; g++) { s += red_s[g * 64 + tid]; q += red_q[g * 64 + tid]; }
        float mean = s * (1.f / 128.f);
        float var  = q * (1.f / 128.f) - mean * mean;
        float rs = rsqrtf(var + EPSV);
        int col = col0 + tid;
        float a = gih[col] * rs;
        alpha[tid] = a;
        beta[tid] = bih[col] + bias[col] - mean * a;
    }
    __syncthreads();
    // stage acc into smem (aliasing xs) for coalesced output
#pragma unroll
    for (int j = 0; j < 4; j++)
#pragma unroll
        for (int i = 0; i < 8; i++)
            st[(cg * 4 + j) * 129 + (bg * 8 + i)] = acc[i][j];
    __syncthreads();
    for (int idx = tid; idx < 64 * 128; idx += 256) {
        int b = idx & 127, c = idx >> 7;
        d_wi[((size_t)t * G4 + col0 + c) * BB + b] = st[c * 129 + b] * alpha[c] + beta[c];
    }
}

// =====================================================================
// Persistent recurrence kernel: one launch per layer, all T steps.
// grid 128 CTAs, block 256. CTA owns 2 h-cols (8 gate columns).
// h broadcast is chunked + double-buffered so L2 traffic overlaps FFMA.
// h stored k-major [t][k][b] -> coalesced 512B stores per column.
// =====================================================================
__launch_bounds__(256, 1) __global__ void recur_kernel(
    const float* __restrict__ Whh_l,
    const float* __restrict__ ghh_l, const float* __restrict__ bhh_l,
    const float* __restrict__ gc_l,  const float* __restrict__ bc_l,
    int out_sel)
{
    extern __shared__ float sm[];
    float* hbuf = sm;                     // [2][64][132] h chunk double buffer
    float* wsm  = sm + 2 * 64 * 132;      // [256][8]    Whh slice
    float* red  = wsm + 2048;             // 96 floats reduction scratch

    float* hsout = out_sel ? d_x1 : d_x0;   // k-major [t][k][b]

    const int tid = threadIdx.x;
    const int hcl = tid >> 7;                // 0/1
    const int b   = tid & 127;
    const int warp = tid >> 5, lane = tid & 31;
    const int hcol = blockIdx.x * 2 + hcl;
    const int f4 = tid & 31;                 // float4 lane for fills

    // Whh slice into smem: wsm[k*8 + q], q = hcl*4 + gate
    for (int idx = tid; idx < 256 * 8; idx += 256) {
        int k = idx >> 3, q = idx & 7;
        int hc = blockIdx.x * 2 + (q >> 2);
        int j = q & 3;
        wsm[idx] = Whh_l[k * G4 + j * HH + hc];
    }

    float ghh[4], bhh[4];
#pragma unroll
    for (int j = 0; j < 4; j++) {
        ghh[j] = ghh_l[j * HH + hcol];
        bhh[j] = bhh_l[j * HH + hcol];
    }
    const float gcv = gc_l[hcol], bcv = bc_l[hcol];
    float c = 0.f;

    // wi for t=0
    float wiv[4];
#pragma unroll
    for (int j = 0; j < 4; j++)
        wiv[j] = d_wi[((size_t)0 * G4 + j * HH + hcol) * BB + b];

    __syncthreads();

    const float4* w4 = (const float4*)wsm;
    volatile unsigned int* vb = &d_bar;

    for (int t = 0; t < TT; t++) {
        float acc[4] = {0.f, 0.f, 0.f, 0.f};
        if (t > 0) {
            const float4* hp4 = (const float4*)(hsout + (size_t)(t - 1) * HH * BB);
            float4* hb4_0 = (float4*)hbuf;
            float4* hb4_1 = (float4*)(hbuf + 64 * 132);
            // prologue: fill chunk 0 (k 0..63)
#pragma unroll
            for (int i = 0; i < 8; i++) {
                int kk = (tid + i * 256) >> 5;
                hb4_0[kk * 33 + f4] = hp4[kk * 32 + f4];
            }
            __syncthreads();
#pragma unroll
            for (int cc = 0; cc < 4; cc++) {
                float4 nxt[8];
                if (cc < 3) {
#pragma unroll
                    for (int i = 0; i < 8; i++) {
                        int kk = (tid + i * 256) >> 5;
                        nxt[i] = hp4[((cc + 1) * 64 + kk) * 32 + f4];
                    }
                }
                const float* hc = hbuf + (cc & 1) * (64 * 132);
                const int kbase = cc * 64;
#pragma unroll 8
                for (int kk = 0; kk < 64; kk++) {
                    float hv = hc[kk * 132 + b];
                    float4 w = w4[(kbase + kk) * 2 + hcl];
                    acc[0] += hv * w.x;
                    acc[1] += hv * w.y;
                    acc[2] += hv * w.z;
                    acc[3] += hv * w.w;
                }
                if (cc < 3) {
                    float4* hn = (cc & 1) ? hb4_0 : hb4_1;
#pragma unroll
                    for (int i = 0; i < 8; i++) {
                        int kk = (tid + i * 256) >> 5;
                        hn[kk * 33 + f4] = nxt[i];
                    }
                    __syncthreads();
                }
            }
        }

        // ---- BN over batch per gate column (group = 4 warps sharing hcl) ----
        float s[4], q[4];
#pragma unroll
        for (int j = 0; j < 4; j++) { s[j] = acc[j]; q[j] = acc[j] * acc[j]; }
#pragma unroll
        for (int o = 16; o; o >>= 1)
#pragma unroll
            for (int j = 0; j < 4; j++) {
                s[j] += __shfl_xor_sync(0xffffffffu, s[j], o);
                q[j] += __shfl_xor_sync(0xffffffffu, q[j], o);
            }
        if (lane == 0)
#pragma unroll
            for (int j = 0; j < 4; j++) {
                red[warp * 8 + j] = s[j];
                red[warp * 8 + 4 + j] = q[j];
            }
        __syncthreads();
        float sg[4];
        {
            float S[4] = {0,0,0,0}, Q[4] = {0,0,0,0};
            int w0 = hcl * 4;
#pragma unroll
            for (int w = 0; w < 4; w++)
#pragma unroll
                for (int j = 0; j < 4; j++) {
                    S[j] += red[(w0 + w) * 8 + j];
                    Q[j] += red[(w0 + w) * 8 + 4 + j];
                }
#pragma unroll
            for (int j = 0; j < 4; j++) {
                float mean = S[j] * (1.f / 128.f);
                float var = Q[j] * (1.f / 128.f) - mean * mean;
                float rs = rsqrtf(var + EPSV);
                sg[j] = (acc[j] - mean) * rs * ghh[j] + bhh[j] + wiv[j];
            }
        }
        // gate order: f, i, o, g
        float fg = sigm(sg[0]);
        float ig = sigm(sg[1]);
        float og = sigm(sg[2]);
        float gg = tanhf(sg[3]);
        c = fg * c + ig * gg;

        // ---- BN(c) over batch per h column ----
        float cs = c, cq = c * c;
#pragma unroll
        for (int o = 16; o; o >>= 1) {
            cs += __shfl_xor_sync(0xffffffffu, cs, o);
            cq += __shfl_xor_sync(0xffffffffu, cq, o);
        }
        if (lane == 0) { red[64 + warp * 2] = cs; red[64 + warp * 2 + 1] = cq; }
        __syncthreads();
        float Sc = 0.f, Qc = 0.f;
        {
            int w0 = hcl * 4;
#pragma unroll
            for (int w = 0; w < 4; w++) { Sc += red[64 + (w0 + w) * 2]; Qc += red[64 + (w0 + w) * 2 + 1]; }
        }
        float mc = Sc * (1.f / 128.f);
        float vc = Qc * (1.f / 128.f) - mc * mc;
        float cn = (c - mc) * rsqrtf(vc + EPSV) * gcv + bcv;
        float h = og * tanhf(cn);

        // coalesced k-major store: [t][hcol][b]
        hsout[(size_t)t * HH * BB + hcol * BB + b] = h;

        if (t < TT - 1) {
            __threadfence();
            __syncthreads();
            if (tid == 0) atomicAdd(&d_bar, 1u);
            // prefetch next step's bn_wi while waiting (independent of barrier)
            float wn0 = d_wi[((size_t)(t + 1) * G4 + 0 * HH + hcol) * BB + b];
            float wn1 = d_wi[((size_t)(t + 1) * G4 + 1 * HH + hcol) * BB + b];
            float wn2 = d_wi[((size_t)(t + 1) * G4 + 2 * HH + hcol) * BB + b];
            float wn3 = d_wi[((size_t)(t + 1) * G4 + 3 * HH + hcol) * BB + b];
            if (tid == 0) {
                unsigned int target = 128u * (unsigned)(t + 1);
                while (*vb < target) { }
                __threadfence();
            }
            __syncthreads();
            wiv[0] = wn0; wiv[1] = wn1; wiv[2] = wn2; wiv[3] = wn3;
        }
    }
}

// =====================================================================
// Final: out = softmax(h_last @ W_lin + b_lin). grid 128 (batch), block 256.
// =====================================================================
__launch_bounds__(256) __global__ void final_kernel(
    int xsel, const float* __restrict__ Wlin, const float* __restrict__ blin,
    float* __restrict__ out)
{
    __shared__ float xr[256];
    __shared__ float lg[CC];
    __shared__ float rbuf[8];
    const float* hs = (xsel ? d_x1 : d_x0);
    int tid = threadIdx.x, warp = tid >> 5, lane = tid & 31;

    // k-major: x[T-1][k][b]
    xr[tid] = hs[(size_t)(TT - 1) * HH * BB + tid * BB + blockIdx.x];
    __syncthreads();

    float lmax = -1e30f;
    for (int cidx = tid; cidx < CC; cidx += 256) {
        float a = blin[cidx];
#pragma unroll 4
        for (int k = 0; k < 256; k++) a += xr[k] * Wlin[k * CC + cidx];
        lg[cidx] = a;
        lmax = fmaxf(lmax, a);
    }
#pragma unroll
    for (int o = 16; o; o >>= 1) lmax = fmaxf(lmax, __shfl_xor_sync(0xffffffffu, lmax, o));
    if (lane == 0) rbuf[warp] = lmax;
    __syncthreads();
    float M = rbuf[0];
#pragma unroll
    for (int w = 1; w < 8; w++) M = fmaxf(M, rbuf[w]);
    __syncthreads();

    float lsum = 0.f;
    for (int cidx = tid; cidx < CC; cidx += 256) {
        float e = __expf(lg[cidx] - M);
        lg[cidx] = e;
        lsum += e;
    }
#pragma unroll
    for (int o = 16; o; o >>= 1) lsum += __shfl_xor_sync(0xffffffffu, lsum, o);
    if (lane == 0) rbuf[warp] = lsum;
    __syncthreads();
    float S = 0.f;
#pragma unroll
    for (int w = 0; w < 8; w++) S += rbuf[w];
    float inv = 1.f / S;
    for (int cidx = tid; cidx < CC; cidx += 256)
        out[blockIdx.x * CC + cidx] = lg[cidx] * inv;
}

// =====================================================================
extern "C" void kernel_launch(void* const* d_in, const int* in_sizes, int n_in,
                              void* d_out, int out_size)
{
    const float* seq  = (const float*)d_in[0];
    const float* Wih0 = (const float*)d_in[1];
    const float* Wih  = (const float*)d_in[2];
    const float* Whh  = (const float*)d_in[3];
    const float* bias = (const float*)d_in[4];
    const float* gih  = (const float*)d_in[5];
    const float* bih  = (const float*)d_in[6];
    const float* ghh  = (const float*)d_in[7];
    const float* bhh  = (const float*)d_in[8];
    const float* gc   = (const float*)d_in[9];
    const float* bc   = (const float*)d_in[10];
    const float* Wlin = (const float*)d_in[11];
    const float* blin = (const float*)d_in[12];
    float* out = (float*)d_out;

    const int PROJ_SMEM  = (8256 + 4160 + 1024 + 1024 + 64 + 64) * 4;   // 58368 B
    const int RECUR_SMEM = (2 * 64 * 132 + 2048 + 96) * 4;              // 76160 B

    cudaFuncSetAttribute((const void*)projbn_kernel,
                         cudaFuncAttributeMaxDynamicSharedMemorySize, PROJ_SMEM);
    cudaFuncSetAttribute((const void*)recur_kernel,
                         cudaFuncAttributeMaxDynamicSharedMemorySize, RECUR_SMEM);

    for (int l = 0; l < LL; l++) {
        const float* Wi = (l == 0) ? Wih0 : (Wih + (size_t)(l - 1) * HH * G4);
        int K = (l == 0) ? II : HH;
        int in_sel = (l == 0) ? -1 : ((l - 1) & 1);
        projbn_kernel<<<dim3(TT, 16), 256, PROJ_SMEM>>>(
            seq, Wi, gih + l * G4, bih + l * G4, bias + l * G4, K, in_sel);
        reset_bar_kernel<<<1, 1>>>();
        recur_kernel<<<128, 256, RECUR_SMEM>>>(
            Whh + (size_t)l * HH * G4,
            ghh + l * G4, bhh + l * G4, gc + l * HH, bc + l * HH, l & 1);
    }
    final_kernel<<<128, 256>>>((LL - 1) & 1, Wlin, blin, out);
}